// round 5
// baseline (speedup 1.0000x reference)
#include <cuda_runtime.h>
#include <cstdint>

typedef unsigned long long u64;
typedef unsigned int u32;

// ---- packed f32x2 math (Blackwell sm_10x; ptxas never auto-generates these) ----
__device__ __forceinline__ u64 f2mul(u64 a, u64 b) {
    u64 d; asm("mul.rn.f32x2 %0, %1, %2;" : "=l"(d) : "l"(a), "l"(b)); return d;
}
__device__ __forceinline__ u64 f2add(u64 a, u64 b) {
    u64 d; asm("add.rn.f32x2 %0, %1, %2;" : "=l"(d) : "l"(a), "l"(b)); return d;
}
__device__ __forceinline__ u64 f2fma(u64 a, u64 b, u64 c) {
    u64 d; asm("fma.rn.f32x2 %0, %1, %2, %3;" : "=l"(d) : "l"(a), "l"(b), "l"(c)); return d;
}
__device__ __forceinline__ u64 dup2(float f) {
    u64 d; asm("mov.b64 %0, {%1, %1};" : "=l"(d) : "f"(f)); return d;
}
// pinned shared load: volatile so ptxas cannot hoist it out of the cc loop
// (hoisting would re-inflate register pressure and kill occupancy).
__device__ __forceinline__ u64 lds64v(u32 a) {
    u64 d; asm volatile("ld.shared.b64 %0, [%1];" : "=l"(d) : "r"(a)); return d;
}
__device__ __forceinline__ u32 s2u(const void* p) {
    return (u32)__cvta_generic_to_shared(p);
}

// packed constants {v, v}
#define HALF2  0x3F0000003F000000ULL   // { 0.5,    0.5   }
#define N8TH2  0xBE000000BE000000ULL   // {-0.125, -0.125 }
#define QURT2  0x3E8000003E800000ULL   // { 0.25,   0.25  }
#define N16T2  0xBD800000BD800000ULL   // {-0.0625,-0.0625}

// mid-level MAJ, 2x-scaled carry: out = 2*maj(A/2,B/2,C/2) = A*(1/2 - BC/8) + (B+C)/2
__device__ __forceinline__ u64 maj_scaled(u64 A, u64 B, u64 C) {
    u64 t = f2mul(B, C);
    u64 u = f2fma(t, N8TH2, HALF2);
    u64 s = f2add(B, C);
    u64 v = f2mul(s, HALF2);
    return f2fma(A, u, v);
}
// top-level: final /2 folded into the constants
__device__ __forceinline__ u64 maj_final(u64 A, u64 B, u64 C) {
    u64 t = f2mul(B, C);
    u64 u = f2fma(t, N16T2, QURT2);
    u64 s = f2add(B, C);
    u64 v = f2mul(s, QURT2);
    return f2fma(A, u, v);
}
// level-1: weights {W0,W1} {W2,Wp=-(W0W1W2)}, patches P0..P2, PP=P0P1P2:
//   2*maj = W0P0 + W1P1 + W2P2 + Wp*PP
__device__ __forceinline__ u64 lvl1(ulonglong2 wa, ulonglong2 wb,
                                    u64 P0, u64 P1, u64 P2, u64 PP) {
    u64 s = f2mul(wb.x, P2);
    s = f2fma(wa.y, P1, s);
    s = f2fma(wa.x, P0, s);
    return f2fma(wb.y, PP, s);
}

// x: [8,3,64,64]  weight: [64,3,3,3]  out: [8,64,64,64]
// Block = 128 threads = 64 w-lanes x 2 co-slots; each thread computes TWO
// vertically-adjacent output rows, batch-pair packed in f32x2, 4 output
// channels. Grid = (32 row-pairs, 4 batch-pairs, 8 co-eighths) = 1024 blocks.
// Register diet: only patch rows 1,2 live in registers; rows 0,3 and the
// triple-products PP are re-read from shared each iteration -> 5 blocks/SM.
__global__ void __launch_bounds__(128, 5)
sconv_maj_kernel(const float* __restrict__ x,
                 const float* __restrict__ wgt,
                 float* __restrict__ out)
{
    __shared__ float2 sP[3][4][66];     // [ch][imgrow h0-1..h0+2][col+1], batch-interleaved
    __shared__ u64 sW4[8][9][4];        // per (co_local, triple): {W0,W1,W2,-(W0W1W2)} dup'd
    __shared__ u64 sPP[12][128];        // per-thread patch triple-products [c*4+r][tid]

    const int tid = threadIdx.x;
    const int h0  = blockIdx.x * 2;      // first output row of the pair
    const int n0  = blockIdx.y * 2;      // batch pair
    const int z   = blockIdx.z;          // co eighth (8 channels)

    // ---- stage input strip (rows h0-1..h0+2, cols -1..64, 3 ch, 2 batches) ----
    #pragma unroll
    for (int it = 0; it < 7; ++it) {
        int idx = tid + it * 128;
        if (idx < 3 * 4 * 66) {
            int c   = idx / 264;
            int rem = idx - c * 264;
            int r   = rem / 66;
            int col = rem - r * 66;
            int hh  = h0 - 1 + r;
            int ww  = col - 1;
            float2 v = make_float2(0.f, 0.f);
            if (hh >= 0 && hh < 64 && ww >= 0 && ww < 64) {
                int off = (c * 64 + hh) * 64 + ww;
                v.x = x[n0 * 12288 + off];
                v.y = x[n0 * 12288 + 12288 + off];
            }
            sP[c][r][col] = v;
        }
    }
    // ---- weight table for this co eighth: {W0,W1,W2,-(W0W1W2)} dup'd ----
    if (tid < 72) {
        int col = tid / 9, q = tid % 9;
        const float* wp = wgt + (z * 8 + col) * 27 + q * 3;
        float w0 = wp[0], w1 = wp[1], w2 = wp[2];
        sW4[col][q][0] = dup2(w0);
        sW4[col][q][1] = dup2(w1);
        sW4[col][q][2] = dup2(w2);
        sW4[col][q][3] = dup2(-(w0 * w1 * w2));
    }
    __syncthreads();

    const int w = tid & 63;    // pixel column
    const int g = tid >> 6;    // co slot (0..1)

    // ---- register cache: rows 1,2 only; PP for all 4 rows -> shared ----
    const u64* Pb = reinterpret_cast<const u64*>(&sP[0][0][0]);
    u64 R1[3][3], R2[3][3];
    #pragma unroll
    for (int c = 0; c < 3; ++c) {
        #pragma unroll
        for (int r = 0; r < 4; ++r) {
            u64 p0 = Pb[(c * 4 + r) * 66 + w + 0];
            u64 p1 = Pb[(c * 4 + r) * 66 + w + 1];
            u64 p2 = Pb[(c * 4 + r) * 66 + w + 2];
            sPP[c * 4 + r][tid] = f2mul(f2mul(p0, p1), p2);
            if (r == 1) { R1[c][0] = p0; R1[c][1] = p1; R1[c][2] = p2; }
            if (r == 2) { R2[c][0] = p0; R2[c][1] = p1; R2[c][2] = p2; }
        }
    }
    // (each thread reads back only its own sPP column -> no __syncthreads needed)

    const u32 sPbase  = s2u(&sP[0][0][0]) + w * 8;     // + j*8 / row stride 66*8
    const u32 sPPbase = s2u(&sPP[0][0]) + tid * 8;     // + (c*4+r)*1024

    const int co0 = z * 8 + g;
    int ob = ((n0 * 64 + co0) * 64 + h0) * 64 + w;
    const ulonglong2* wv = reinterpret_cast<const ulonglong2*>(&sW4[g][0][0]);

    #pragma unroll 2
    for (int cc = 0; cc < 4; ++cc) {
        u64 m2a[3], m2b[3];
        #pragma unroll
        for (int c = 0; c < 3; ++c) {
            // pinned per-iteration shared reads (rows 0 and 3, and the 4 PPs)
            const u32 rowA = sPbase + (c * 4 + 0) * (66 * 8);
            const u32 rowB = sPbase + (c * 4 + 3) * (66 * 8);
            u64 a0 = lds64v(rowA), a1 = lds64v(rowA + 8), a2 = lds64v(rowA + 16);
            u64 b0 = lds64v(rowB), b1 = lds64v(rowB + 8), b2 = lds64v(rowB + 16);
            u64 pp0 = lds64v(sPPbase + (c * 4 + 0) * 1024);
            u64 pp1 = lds64v(sPPbase + (c * 4 + 1) * 1024);
            u64 pp2 = lds64v(sPPbase + (c * 4 + 2) * 1024);
            u64 pp3 = lds64v(sPPbase + (c * 4 + 3) * 1024);

            ulonglong2 wa0 = wv[2*(c*3+0)], wb0 = wv[2*(c*3+0)+1];
            ulonglong2 wa1 = wv[2*(c*3+1)], wb1 = wv[2*(c*3+1)+1];
            ulonglong2 wa2 = wv[2*(c*3+2)], wb2 = wv[2*(c*3+2)+1];

            u64 l1a0 = lvl1(wa0, wb0, a0, a1, a2, pp0);
            u64 l1a1 = lvl1(wa1, wb1, R1[c][0], R1[c][1], R1[c][2], pp1);
            u64 l1a2 = lvl1(wa2, wb2, R2[c][0], R2[c][1], R2[c][2], pp2);
            u64 l1b0 = lvl1(wa0, wb0, R1[c][0], R1[c][1], R1[c][2], pp1);
            u64 l1b1 = lvl1(wa1, wb1, R2[c][0], R2[c][1], R2[c][2], pp2);
            u64 l1b2 = lvl1(wa2, wb2, b0, b1, b2, pp3);

            m2a[c] = maj_scaled(l1a0, l1a1, l1a2);
            m2b[c] = maj_scaled(l1b0, l1b1, l1b2);
        }
        u64 ra = maj_final(m2a[0], m2a[1], m2a[2]);
        u64 rb = maj_final(m2b[0], m2b[1], m2b[2]);

        float2 fa, fb;
        asm("mov.b64 {%0, %1}, %2;" : "=f"(fa.x), "=f"(fa.y) : "l"(ra));
        asm("mov.b64 {%0, %1}, %2;" : "=f"(fb.x), "=f"(fb.y) : "l"(rb));
        out[ob]               = fa.x;    // batch n0,   row h0
        out[ob + 64]          = fb.x;    // batch n0,   row h0+1
        out[ob + 262144]      = fa.y;    // batch n0+1, row h0
        out[ob + 262144 + 64] = fb.y;    // batch n0+1, row h0+1

        ob += 2 * 4096;                  // co += 2
        wv += 2 * 18;                    // 18 ulonglong2 per co
    }
}

extern "C" void kernel_launch(void* const* d_in, const int* in_sizes, int n_in,
                              void* d_out, int out_size)
{
    const float* x   = (const float*)d_in[0];   // [8,3,64,64]
    const float* wgt = (const float*)d_in[1];   // [64,3,3,3]
    float* out = (float*)d_out;                 // [8,64,64,64]

    dim3 grid(32, 4, 8);   // 32 row-pairs x 4 batch-pairs x 8 co-eighths
    sconv_maj_kernel<<<grid, 128>>>(x, wgt, out);
}

// round 6
// speedup vs baseline: 1.5923x; 1.5923x over previous
#include <cuda_runtime.h>
#include <cstdint>

typedef unsigned long long u64;

// ---- packed f32x2 math (Blackwell sm_10x; ptxas never auto-generates these) ----
__device__ __forceinline__ u64 f2mul(u64 a, u64 b) {
    u64 d; asm("mul.rn.f32x2 %0, %1, %2;" : "=l"(d) : "l"(a), "l"(b)); return d;
}
__device__ __forceinline__ u64 f2add(u64 a, u64 b) {
    u64 d; asm("add.rn.f32x2 %0, %1, %2;" : "=l"(d) : "l"(a), "l"(b)); return d;
}
__device__ __forceinline__ u64 f2fma(u64 a, u64 b, u64 c) {
    u64 d; asm("fma.rn.f32x2 %0, %1, %2, %3;" : "=l"(d) : "l"(a), "l"(b), "l"(c)); return d;
}
__device__ __forceinline__ u64 dup2(float f) {
    u64 d; asm("mov.b64 %0, {%1, %1};" : "=l"(d) : "f"(f)); return d;
}

// packed constants {v, v}
#define ONE2   0x3F8000003F800000ULL   // { 1.0,    1.0   }
#define N4TH2  0xBE800000BE800000ULL   // {-0.25,  -0.25  }
#define N16T2  0xBD800000BD800000ULL   // {-0.0625,-0.0625}
#define EGTH2  0x3E0000003E000000ULL   // { 0.125,  0.125 }

// Scale-doubling MAJ ladder: inputs scaled k (A = k*a), output scaled 2k:
//   2k*maj(a,b,c) = (A+B+C) - ABC/k^2   -> 4 ops with K = -1/k^2
// level-2: k=2 -> K=-1/4;  level-3: k=4 -> K=-1/16; final result = out/8.
__device__ __forceinline__ u64 maj_lvl(u64 A, u64 B, u64 C, u64 K) {
    u64 t = f2mul(B, C);
    u64 u = f2fma(t, K, ONE2);
    u64 s = f2add(B, C);
    return f2fma(A, u, s);
}
// level-1: weights {W0,W1} {W2,Wp=-(W0W1W2)}, patches P0..P2, PP=P0P1P2:
//   2*maj = W0P0 + W1P1 + W2P2 + Wp*PP   (4 ops, k_out = 2)
__device__ __forceinline__ u64 lvl1(ulonglong2 wa, ulonglong2 wb,
                                    u64 P0, u64 P1, u64 P2, u64 PP) {
    u64 s = f2mul(wb.x, P2);
    s = f2fma(wa.y, P1, s);
    s = f2fma(wa.x, P0, s);
    return f2fma(wb.y, PP, s);
}

// x: [8,3,64,64]  weight: [64,3,3,3]  out: [8,64,64,64]
// Block = 128 threads = 64 w-lanes x 2 co-slots; each thread computes TWO
// vertically-adjacent output rows, batch-pair packed in f32x2, 4 output
// channels (fully unrolled). Grid = (32 row-pairs, 4 batch-pairs, 8 co-eighths).
__global__ void __launch_bounds__(128, 4)
sconv_maj_kernel(const float* __restrict__ x,
                 const float* __restrict__ wgt,
                 float* __restrict__ out)
{
    __shared__ float2 sP[3][4][66];     // [ch][imgrow h0-1..h0+2][col+1], batch-interleaved
    __shared__ u64 sW4[8][9][4];        // per (co_local, triple): {W0,W1,W2,-(W0W1W2)} dup'd

    const int tid = threadIdx.x;
    const int h0  = blockIdx.x * 2;      // first output row of the pair
    const int n0  = blockIdx.y * 2;      // batch pair
    const int z   = blockIdx.z;          // co eighth (8 channels)

    // ---- stage input strip (rows h0-1..h0+2, cols -1..64, 3 ch, 2 batches) ----
    #pragma unroll
    for (int it = 0; it < 7; ++it) {
        int idx = tid + it * 128;
        if (idx < 3 * 4 * 66) {
            int c   = idx / 264;
            int rem = idx - c * 264;
            int r   = rem / 66;
            int col = rem - r * 66;
            int hh  = h0 - 1 + r;
            int ww  = col - 1;
            float2 v = make_float2(0.f, 0.f);
            if (hh >= 0 && hh < 64 && ww >= 0 && ww < 64) {
                int off = (c * 64 + hh) * 64 + ww;
                v.x = x[n0 * 12288 + off];
                v.y = x[n0 * 12288 + 12288 + off];
            }
            sP[c][r][col] = v;
        }
    }
    // ---- weight table for this co eighth: {W0,W1,W2,-(W0W1W2)} dup'd ----
    if (tid < 72) {
        int col = tid / 9, q = tid % 9;
        const float* wp = wgt + (z * 8 + col) * 27 + q * 3;
        float w0 = wp[0], w1 = wp[1], w2 = wp[2];
        sW4[col][q][0] = dup2(w0);
        sW4[col][q][1] = dup2(w1);
        sW4[col][q][2] = dup2(w2);
        sW4[col][q][3] = dup2(-(w0 * w1 * w2));
    }
    __syncthreads();

    const int w = tid & 63;    // pixel column
    const int g = tid >> 6;    // co slot (0..1)

    // ---- register-cache 36 packed patches (3ch x 4rows x 3cols) + 12 row-products ----
    const u64* Pb = reinterpret_cast<const u64*>(&sP[0][0][0]);
    u64 P[3][4][3], PP[3][4];
    #pragma unroll
    for (int c = 0; c < 3; ++c)
        #pragma unroll
        for (int r = 0; r < 4; ++r) {
            #pragma unroll
            for (int j = 0; j < 3; ++j)
                P[c][r][j] = Pb[(c * 4 + r) * 66 + w + j];
            PP[c][r] = f2mul(f2mul(P[c][r][0], P[c][r][1]), P[c][r][2]);
        }

    const int co0 = z * 8 + g;
    const int ob  = ((n0 * 64 + co0) * 64 + h0) * 64 + w;
    const ulonglong2* wv = reinterpret_cast<const ulonglong2*>(&sW4[g][0][0]);

    #pragma unroll
    for (int cc = 0; cc < 4; ++cc) {     // co = co0 + 2*cc ; all offsets compile-time
        u64 m2a[3], m2b[3];
        #pragma unroll
        for (int c = 0; c < 3; ++c) {
            u64 l1a[3], l1b[3];
            #pragma unroll
            for (int kr = 0; kr < 3; ++kr) {
                const int q = c * 3 + kr;
                ulonglong2 wa = wv[cc * 36 + 2 * q];       // {W0, W1}
                ulonglong2 wb = wv[cc * 36 + 2 * q + 1];   // {W2, -(W0W1W2)}
                l1a[kr] = lvl1(wa, wb, P[c][kr  ][0], P[c][kr  ][1], P[c][kr  ][2], PP[c][kr  ]);
                l1b[kr] = lvl1(wa, wb, P[c][kr+1][0], P[c][kr+1][1], P[c][kr+1][2], PP[c][kr+1]);
            }
            m2a[c] = maj_lvl(l1a[0], l1a[1], l1a[2], N4TH2);   // out = 4*maj
            m2b[c] = maj_lvl(l1b[0], l1b[1], l1b[2], N4TH2);
        }
        u64 ra = f2mul(maj_lvl(m2a[0], m2a[1], m2a[2], N16T2), EGTH2);  // (8*maj)/8
        u64 rb = f2mul(maj_lvl(m2b[0], m2b[1], m2b[2], N16T2), EGTH2);

        float2 fa, fb;
        asm("mov.b64 {%0, %1}, %2;" : "=f"(fa.x), "=f"(fa.y) : "l"(ra));
        asm("mov.b64 {%0, %1}, %2;" : "=f"(fb.x), "=f"(fb.y) : "l"(rb));
        out[ob + cc * 8192]               = fa.x;    // batch n0,   row h0
        out[ob + cc * 8192 + 64]          = fb.x;    // batch n0,   row h0+1
        out[ob + cc * 8192 + 262144]      = fa.y;    // batch n0+1, row h0
        out[ob + cc * 8192 + 262144 + 64] = fb.y;    // batch n0+1, row h0+1
    }
}

extern "C" void kernel_launch(void* const* d_in, const int* in_sizes, int n_in,
                              void* d_out, int out_size)
{
    const float* x   = (const float*)d_in[0];   // [8,3,64,64]
    const float* wgt = (const float*)d_in[1];   // [64,3,3,3]
    float* out = (float*)d_out;                 // [8,64,64,64]

    dim3 grid(32, 4, 8);   // 32 row-pairs x 4 batch-pairs x 8 co-eighths
    sconv_maj_kernel<<<grid, 128>>>(x, wgt, out);
}

// round 7
// speedup vs baseline: 1.5970x; 1.0030x over previous
#include <cuda_runtime.h>
#include <cstdint>

typedef unsigned long long u64;

// ---- packed f32x2 math (Blackwell sm_10x; ptxas never auto-generates these) ----
__device__ __forceinline__ u64 f2mul(u64 a, u64 b) {
    u64 d; asm("mul.rn.f32x2 %0, %1, %2;" : "=l"(d) : "l"(a), "l"(b)); return d;
}
__device__ __forceinline__ u64 f2add(u64 a, u64 b) {
    u64 d; asm("add.rn.f32x2 %0, %1, %2;" : "=l"(d) : "l"(a), "l"(b)); return d;
}
__device__ __forceinline__ u64 f2fma(u64 a, u64 b, u64 c) {
    u64 d; asm("fma.rn.f32x2 %0, %1, %2, %3;" : "=l"(d) : "l"(a), "l"(b), "l"(c)); return d;
}
__device__ __forceinline__ u64 dup2(float f) {
    u64 d; asm("mov.b64 %0, {%1, %1};" : "=l"(d) : "f"(f)); return d;
}

// packed constants {v, v}
#define ONE2   0x3F8000003F800000ULL   // {  1.0,   1.0 }
#define KL2    0xC1800000C1800000ULL   // {-16.0, -16.0 }
#define KL3    0xC0800000C0800000ULL   // { -4.0,  -4.0 }

// Scale-carrying MAJ ladder. Level-1 weights are pre-scaled by s=1/8 in the
// table, so level-1 outputs carry k1 = 2s = 1/4, level-2 outputs k2 = 1/2,
// level-3 outputs k3 = 1 (no final multiply).
//   out = (A+B+C) + A*B*C*K  with K = -1/k_in^2  -> 4 ops
__device__ __forceinline__ u64 maj_lvl(u64 A, u64 B, u64 C, u64 K) {
    u64 t = f2mul(B, C);
    u64 u = f2fma(t, K, ONE2);
    u64 s = f2add(B, C);
    return f2fma(A, u, s);
}
// level-1: weights {sW0,sW1} {sW2,Wp=-s*(W0W1W2)}, patches P0..P2, PP=P0P1P2:
//   s*2*maj = sW0P0 + sW1P1 + sW2P2 + Wp*PP   (4 ops, out scale 2s = 1/4)
__device__ __forceinline__ u64 lvl1(ulonglong2 wa, ulonglong2 wb,
                                    u64 P0, u64 P1, u64 P2, u64 PP) {
    u64 s = f2mul(wb.x, P2);
    s = f2fma(wa.y, P1, s);
    s = f2fma(wa.x, P0, s);
    return f2fma(wb.y, PP, s);
}

// x: [8,3,64,64]  weight: [64,3,3,3]  out: [8,64,64,64]
// Block = 128 threads = 64 w-lanes x 2 co-slots; each thread computes TWO
// vertically-adjacent output rows, batch-pair packed in f32x2, 4 output
// channels. Channel-outer loop: only the current channel's 12 patches + 4
// triple-products stay in registers; level-2 partials m2[cc] carry across.
// Grid = (32 row-pairs, 4 batch-pairs, 8 co-eighths) = 1024 blocks.
__global__ void __launch_bounds__(128, 4)
sconv_maj_kernel(const float* __restrict__ x,
                 const float* __restrict__ wgt,
                 float* __restrict__ out)
{
    __shared__ float2 sP[3][4][66];     // [ch][imgrow h0-1..h0+2][col+1], batch-interleaved
    __shared__ u64 sW4[8][9][4];        // per (co_local, triple): {sW0,sW1,sW2,-s*W0W1W2} dup'd

    const int tid = threadIdx.x;
    const int h0  = blockIdx.x * 2;      // first output row of the pair
    const int n0  = blockIdx.y * 2;      // batch pair
    const int z   = blockIdx.z;          // co eighth (8 channels)

    // ---- stage input strip (rows h0-1..h0+2, cols -1..64, 3 ch, 2 batches) ----
    #pragma unroll
    for (int it = 0; it < 7; ++it) {
        int idx = tid + it * 128;
        if (idx < 3 * 4 * 66) {
            int c   = idx / 264;
            int rem = idx - c * 264;
            int r   = rem / 66;
            int col = rem - r * 66;
            int hh  = h0 - 1 + r;
            int ww  = col - 1;
            float2 v = make_float2(0.f, 0.f);
            if (hh >= 0 && hh < 64 && ww >= 0 && ww < 64) {
                int off = (c * 64 + hh) * 64 + ww;
                v.x = x[n0 * 12288 + off];
                v.y = x[n0 * 12288 + 12288 + off];
            }
            sP[c][r][col] = v;
        }
    }
    // ---- weight table for this co eighth, pre-scaled by s = 1/8 ----
    if (tid < 72) {
        int col = tid / 9, q = tid % 9;
        const float* wp = wgt + (z * 8 + col) * 27 + q * 3;
        float w0 = wp[0], w1 = wp[1], w2 = wp[2];
        const float s = 0.125f;
        sW4[col][q][0] = dup2(w0 * s);
        sW4[col][q][1] = dup2(w1 * s);
        sW4[col][q][2] = dup2(w2 * s);
        sW4[col][q][3] = dup2(-(w0 * w1 * w2) * s);
    }
    __syncthreads();

    const int w = tid & 63;    // pixel column
    const int g = tid >> 6;    // co slot (0..1)

    const u64* Pb = reinterpret_cast<const u64*>(&sP[0][0][0]);
    const ulonglong2* wv = reinterpret_cast<const ulonglong2*>(&sW4[g][0][0]);

    u64 m2a[4][3], m2b[4][3];   // level-2 partials [cc][channel], scale 1/2

    #pragma unroll
    for (int c = 0; c < 3; ++c) {
        // ---- current channel's 12 patches + 4 row triple-products ----
        u64 P[4][3], PPr[4];
        #pragma unroll
        for (int r = 0; r < 4; ++r) {
            #pragma unroll
            for (int j = 0; j < 3; ++j)
                P[r][j] = Pb[(c * 4 + r) * 66 + w + j];
            PPr[r] = f2mul(f2mul(P[r][0], P[r][1]), P[r][2]);
        }
        #pragma unroll
        for (int cc = 0; cc < 4; ++cc) {
            u64 l1a[3], l1b[3];
            #pragma unroll
            for (int kr = 0; kr < 3; ++kr) {
                const int q = c * 3 + kr;
                ulonglong2 wa = wv[cc * 36 + 2 * q];       // {sW0, sW1}
                ulonglong2 wb = wv[cc * 36 + 2 * q + 1];   // {sW2, -s*W0W1W2}
                l1a[kr] = lvl1(wa, wb, P[kr  ][0], P[kr  ][1], P[kr  ][2], PPr[kr  ]);
                l1b[kr] = lvl1(wa, wb, P[kr+1][0], P[kr+1][1], P[kr+1][2], PPr[kr+1]);
            }
            m2a[cc][c] = maj_lvl(l1a[0], l1a[1], l1a[2], KL2);   // scale 1/2
            m2b[cc][c] = maj_lvl(l1b[0], l1b[1], l1b[2], KL2);
        }
    }

    const int co0 = z * 8 + g;
    const int ob  = ((n0 * 64 + co0) * 64 + h0) * 64 + w;

    #pragma unroll
    for (int cc = 0; cc < 4; ++cc) {     // co = co0 + 2*cc
        u64 ra = maj_lvl(m2a[cc][0], m2a[cc][1], m2a[cc][2], KL3);  // scale 1 = true maj
        u64 rb = maj_lvl(m2b[cc][0], m2b[cc][1], m2b[cc][2], KL3);

        float2 fa, fb;
        asm("mov.b64 {%0, %1}, %2;" : "=f"(fa.x), "=f"(fa.y) : "l"(ra));
        asm("mov.b64 {%0, %1}, %2;" : "=f"(fb.x), "=f"(fb.y) : "l"(rb));
        out[ob + cc * 8192]               = fa.x;    // batch n0,   row h0
        out[ob + cc * 8192 + 64]          = fb.x;    // batch n0,   row h0+1
        out[ob + cc * 8192 + 262144]      = fa.y;    // batch n0+1, row h0
        out[ob + cc * 8192 + 262144 + 64] = fb.y;    // batch n0+1, row h0+1
    }
}

extern "C" void kernel_launch(void* const* d_in, const int* in_sizes, int n_in,
                              void* d_out, int out_size)
{
    const float* x   = (const float*)d_in[0];   // [8,3,64,64]
    const float* wgt = (const float*)d_in[1];   // [64,3,3,3]
    float* out = (float*)d_out;                 // [8,64,64,64]

    dim3 grid(32, 4, 8);   // 32 row-pairs x 4 batch-pairs x 8 co-eighths
    sconv_maj_kernel<<<grid, 128>>>(x, wgt, out);
}